// round 1
// baseline (speedup 1.0000x reference)
#include <cuda_runtime.h>
#include <math.h>

// Problem constants
#define T     8192
#define DIM   1024
#define NEXP  8
#define HID   2048

// GEMM tiling
#define BM 128
#define BN 128
#define BK 16

// Padded row capacity for the H scratch: exact total rows (T*2) + per-expert
// round-up slack (each of 8 segments padded to a BM multiple).
#define ROWS_CAP (T * 2 + NEXP * BM)

// Scratch (allocation-free rule: __device__ globals). ~143 MB for g_H.
__device__ float g_H[(size_t)ROWS_CAP * HID];
__device__ int   g_tok[NEXP * T];
__device__ float g_wt[NEXP * T];
__device__ int   g_cnt[NEXP];
__device__ int   g_off[NEXP];

// ---------------------------------------------------------------------------
// Zero the dense output region (atomic-accumulated later) and expert counts.
// ---------------------------------------------------------------------------
__global__ void zero_kernel(float* __restrict__ out) {
    size_t i = (size_t)blockIdx.x * blockDim.x + threadIdx.x;
    const size_t n4 = (size_t)T * DIM / 4;
    float4 z = make_float4(0.f, 0.f, 0.f, 0.f);
    for (size_t p = i; p < n4; p += (size_t)gridDim.x * blockDim.x)
        reinterpret_cast<float4*>(out)[p] = z;
    if (i < NEXP) g_cnt[i] = 0;
}

// ---------------------------------------------------------------------------
// Gating: one warp per token. logits = x @ gate_w^T + gate_b, top-2 softmax
// weights, compaction into per-expert token lists.
// ---------------------------------------------------------------------------
__global__ __launch_bounds__(256) void gate_kernel(
    const float* __restrict__ x, const float* __restrict__ gw,
    const float* __restrict__ gb, float* __restrict__ logits_out)
{
    int warp = (int)((blockIdx.x * blockDim.x + threadIdx.x) >> 5);
    int lane = threadIdx.x & 31;
    if (warp >= T) return;

    const float4* xr = reinterpret_cast<const float4*>(x + (size_t)warp * DIM);
    float acc[NEXP];
#pragma unroll
    for (int e = 0; e < NEXP; e++) acc[e] = 0.f;

    for (int i = lane; i < DIM / 4; i += 32) {
        float4 xv = xr[i];
#pragma unroll
        for (int e = 0; e < NEXP; e++) {
            float4 wv = reinterpret_cast<const float4*>(gw + (size_t)e * DIM)[i];
            acc[e] += xv.x * wv.x + xv.y * wv.y + xv.z * wv.z + xv.w * wv.w;
        }
    }
#pragma unroll
    for (int off = 16; off > 0; off >>= 1) {
#pragma unroll
        for (int e = 0; e < NEXP; e++)
            acc[e] += __shfl_xor_sync(0xffffffffu, acc[e], off);
    }

    if (lane == 0) {
        float lg[NEXP];
#pragma unroll
        for (int e = 0; e < NEXP; e++) lg[e] = acc[e] + gb[e];

        // top-2 by logit (softmax is monotone); ties -> lower index like lax.top_k
        int i0 = 0;
#pragma unroll
        for (int e = 1; e < NEXP; e++) if (lg[e] > lg[i0]) i0 = e;
        int i1 = (i0 == 0) ? 1 : 0;
#pragma unroll
        for (int e = 0; e < NEXP; e++)
            if (e != i0 && lg[e] > lg[i1]) i1 = e;

        // normalized top-2 weights: w0 = p0/(p0+p1) = 1/(1+exp(lg1-lg0))
        float w0 = 1.0f / (1.0f + __expf(lg[i1] - lg[i0]));
        // use precise expf for accuracy
        w0 = 1.0f / (1.0f + expf(lg[i1] - lg[i0]));
        float w1 = 1.0f - w0;

        int s0 = atomicAdd(&g_cnt[i0], 1);
        g_tok[i0 * T + s0] = warp;
        g_wt [i0 * T + s0] = w0;
        int s1 = atomicAdd(&g_cnt[i1], 1);
        g_tok[i1 * T + s1] = warp;
        g_wt [i1 * T + s1] = w1;

#pragma unroll
        for (int e = 0; e < NEXP; e++)
            logits_out[(size_t)warp * NEXP + e] = lg[e];
    }
}

// ---------------------------------------------------------------------------
// Segment offsets padded to BM multiples (single thread; 8 entries).
// ---------------------------------------------------------------------------
__global__ void offsets_kernel() {
    if (threadIdx.x == 0 && blockIdx.x == 0) {
        int off = 0;
        for (int e = 0; e < NEXP; e++) {
            g_off[e] = off;
            off += ((g_cnt[e] + BM - 1) / BM) * BM;
        }
    }
}

// ---------------------------------------------------------------------------
// GEMM1: H[rows, HID] = gelu( gather(x)[rows, DIM] @ W1_e[DIM, HID] + b1_e )
// 128x128 tile, BK=16, 256 threads, 8x8 micro-tile.
// ---------------------------------------------------------------------------
__global__ __launch_bounds__(256) void ffn1_kernel(
    const float* __restrict__ x, const float* __restrict__ W1,
    const float* __restrict__ b1)
{
    int e   = blockIdx.z;
    int cnt = g_cnt[e];
    int m0  = blockIdx.y * BM;
    if (m0 >= cnt) return;
    int n0   = blockIdx.x * BN;
    int base = g_off[e];

    __shared__ float As[BK][BM + 4];
    __shared__ float Bs[BK][BN + 4];

    int tid = threadIdx.x;
    int tx = tid & 15, ty = tid >> 4;

    // A-load: each thread handles 2 float4 (rows r0, r1; k-quarter q)
    int r0 = tid >> 2;          // 0..63
    int r1 = 64 + r0;
    int q  = (tid & 3) * 4;
    int tokA0 = (m0 + r0 < cnt) ? g_tok[e * T + m0 + r0] : -1;
    int tokA1 = (m0 + r1 < cnt) ? g_tok[e * T + m0 + r1] : -1;

    const float* Wb = W1 + (size_t)e * DIM * HID + n0;

    float acc[8][8];
#pragma unroll
    for (int i = 0; i < 8; i++)
#pragma unroll
        for (int j = 0; j < 8; j++) acc[i][j] = 0.f;

    for (int k0 = 0; k0 < DIM; k0 += BK) {
        float4 av0 = make_float4(0.f, 0.f, 0.f, 0.f), av1 = av0;
        if (tokA0 >= 0) av0 = *reinterpret_cast<const float4*>(x + (size_t)tokA0 * DIM + k0 + q);
        if (tokA1 >= 0) av1 = *reinterpret_cast<const float4*>(x + (size_t)tokA1 * DIM + k0 + q);
        As[q + 0][r0] = av0.x; As[q + 1][r0] = av0.y; As[q + 2][r0] = av0.z; As[q + 3][r0] = av0.w;
        As[q + 0][r1] = av1.x; As[q + 1][r1] = av1.y; As[q + 2][r1] = av1.z; As[q + 3][r1] = av1.w;

#pragma unroll
        for (int i = 0; i < 2; i++) {
            int j  = tid + i * 256;
            int kr = j >> 5;
            int c4 = (j & 31) * 4;
            *reinterpret_cast<float4*>(&Bs[kr][c4]) =
                *reinterpret_cast<const float4*>(Wb + (size_t)(k0 + kr) * HID + c4);
        }
        __syncthreads();

#pragma unroll
        for (int kk = 0; kk < BK; kk++) {
            float4 a0 = *reinterpret_cast<float4*>(&As[kk][ty * 8]);
            float4 a1 = *reinterpret_cast<float4*>(&As[kk][ty * 8 + 4]);
            float4 b0 = *reinterpret_cast<float4*>(&Bs[kk][tx * 8]);
            float4 b1v = *reinterpret_cast<float4*>(&Bs[kk][tx * 8 + 4]);
            float a[8] = {a0.x, a0.y, a0.z, a0.w, a1.x, a1.y, a1.z, a1.w};
            float b[8] = {b0.x, b0.y, b0.z, b0.w, b1v.x, b1v.y, b1v.z, b1v.w};
#pragma unroll
            for (int i = 0; i < 8; i++)
#pragma unroll
                for (int j = 0; j < 8; j++)
                    acc[i][j] += a[i] * b[j];
        }
        __syncthreads();
    }

    // Epilogue: bias + exact GELU, write H scratch (vectorized)
    float4 bi0 = *reinterpret_cast<const float4*>(b1 + (size_t)e * HID + n0 + tx * 8);
    float4 bi1 = *reinterpret_cast<const float4*>(b1 + (size_t)e * HID + n0 + tx * 8 + 4);
    float bias[8] = {bi0.x, bi0.y, bi0.z, bi0.w, bi1.x, bi1.y, bi1.z, bi1.w};

#pragma unroll
    for (int i = 0; i < 8; i++) {
        int gm = m0 + ty * 8 + i;
        if (gm < cnt) {
            float* hr = g_H + ((size_t)(base + gm)) * HID + n0 + tx * 8;
            float v[8];
#pragma unroll
            for (int j = 0; j < 8; j++) {
                float t = acc[i][j] + bias[j];
                v[j] = 0.5f * t * (1.0f + erff(t * 0.7071067811865476f));
            }
            *reinterpret_cast<float4*>(hr)     = make_float4(v[0], v[1], v[2], v[3]);
            *reinterpret_cast<float4*>(hr + 4) = make_float4(v[4], v[5], v[6], v[7]);
        }
    }
}

// ---------------------------------------------------------------------------
// GEMM2: y = H[rows, HID] @ W2_e[HID, DIM] + b2_e; scatter-add w * y into out.
// ---------------------------------------------------------------------------
__global__ __launch_bounds__(256) void ffn2_kernel(
    const float* __restrict__ W2, const float* __restrict__ b2,
    float* __restrict__ out)
{
    int e   = blockIdx.z;
    int cnt = g_cnt[e];
    int m0  = blockIdx.y * BM;
    if (m0 >= cnt) return;
    int n0   = blockIdx.x * BN;
    int base = g_off[e];

    __shared__ float As[BK][BM + 4];
    __shared__ float Bs[BK][BN + 4];

    int tid = threadIdx.x;
    int tx = tid & 15, ty = tid >> 4;

    int r0 = tid >> 2;
    int r1 = 64 + r0;
    int q  = (tid & 3) * 4;
    bool v0 = (m0 + r0 < cnt);
    bool v1 = (m0 + r1 < cnt);
    const float* A0 = g_H + ((size_t)(base + m0 + r0)) * HID;
    const float* A1 = g_H + ((size_t)(base + m0 + r1)) * HID;

    const float* Wb = W2 + (size_t)e * HID * DIM + n0;

    float acc[8][8];
#pragma unroll
    for (int i = 0; i < 8; i++)
#pragma unroll
        for (int j = 0; j < 8; j++) acc[i][j] = 0.f;

    for (int k0 = 0; k0 < HID; k0 += BK) {
        float4 av0 = make_float4(0.f, 0.f, 0.f, 0.f), av1 = av0;
        if (v0) av0 = *reinterpret_cast<const float4*>(A0 + k0 + q);
        if (v1) av1 = *reinterpret_cast<const float4*>(A1 + k0 + q);
        As[q + 0][r0] = av0.x; As[q + 1][r0] = av0.y; As[q + 2][r0] = av0.z; As[q + 3][r0] = av0.w;
        As[q + 0][r1] = av1.x; As[q + 1][r1] = av1.y; As[q + 2][r1] = av1.z; As[q + 3][r1] = av1.w;

#pragma unroll
        for (int i = 0; i < 2; i++) {
            int j  = tid + i * 256;
            int kr = j >> 5;
            int c4 = (j & 31) * 4;
            *reinterpret_cast<float4*>(&Bs[kr][c4]) =
                *reinterpret_cast<const float4*>(Wb + (size_t)(k0 + kr) * DIM + c4);
        }
        __syncthreads();

#pragma unroll
        for (int kk = 0; kk < BK; kk++) {
            float4 a0 = *reinterpret_cast<float4*>(&As[kk][ty * 8]);
            float4 a1 = *reinterpret_cast<float4*>(&As[kk][ty * 8 + 4]);
            float4 b0 = *reinterpret_cast<float4*>(&Bs[kk][tx * 8]);
            float4 b1v = *reinterpret_cast<float4*>(&Bs[kk][tx * 8 + 4]);
            float a[8] = {a0.x, a0.y, a0.z, a0.w, a1.x, a1.y, a1.z, a1.w};
            float b[8] = {b0.x, b0.y, b0.z, b0.w, b1v.x, b1v.y, b1v.z, b1v.w};
#pragma unroll
            for (int i = 0; i < 8; i++)
#pragma unroll
                for (int j = 0; j < 8; j++)
                    acc[i][j] += a[i] * b[j];
        }
        __syncthreads();
    }

    float4 bi0 = *reinterpret_cast<const float4*>(b2 + (size_t)e * DIM + n0 + tx * 8);
    float4 bi1 = *reinterpret_cast<const float4*>(b2 + (size_t)e * DIM + n0 + tx * 8 + 4);
    float bias[8] = {bi0.x, bi0.y, bi0.z, bi0.w, bi1.x, bi1.y, bi1.z, bi1.w};

#pragma unroll
    for (int i = 0; i < 8; i++) {
        int gm = m0 + ty * 8 + i;
        if (gm < cnt) {
            int tok  = g_tok[e * T + gm];
            float w  = g_wt [e * T + gm];
            float* orow = out + (size_t)tok * DIM + n0 + tx * 8;
#pragma unroll
            for (int j = 0; j < 8; j++)
                atomicAdd(orow + j, w * (acc[i][j] + bias[j]));
        }
    }
}

// ---------------------------------------------------------------------------
// Launch
// ---------------------------------------------------------------------------
extern "C" void kernel_launch(void* const* d_in, const int* in_sizes, int n_in,
                              void* d_out, int out_size) {
    const float* x  = (const float*)d_in[0];
    const float* gw = (const float*)d_in[1];
    const float* gb = (const float*)d_in[2];
    const float* W1 = (const float*)d_in[3];
    const float* b1 = (const float*)d_in[4];
    const float* W2 = (const float*)d_in[5];
    const float* b2 = (const float*)d_in[6];
    float* out = (float*)d_out;

    zero_kernel<<<2048, 256>>>(out);
    gate_kernel<<<T / 8, 256>>>(x, gw, gb, out + (size_t)T * DIM);
    offsets_kernel<<<1, 32>>>();
    ffn1_kernel<<<dim3(HID / BN, T / BM, NEXP), 256>>>(x, W1, b1);
    ffn2_kernel<<<dim3(DIM / BN, T / BM, NEXP), 256>>>(W2, b2, out);
}

// round 9
// speedup vs baseline: 1.8534x; 1.8534x over previous
#include <cuda_runtime.h>
#include <math.h>
#include <stdint.h>

#define T     8192
#define DIM   1024
#define NEXP  8
#define HID   2048

#define BM 64
#define BN 64
#define BK 32
#define ROWS_CAP (T * 2 + NEXP * 128)

// smem stage layout (bytes), static:
//   Ahi: 64 rows x 80   = 5120   (32 k bf16 = 64B, pad to 80)
//   Alo: +5120
//   Bhi: 32 k-rows x 144 = 4608  (64 n bf16 = 128B, pad to 144), at 10240
//   Blo: +4608
#define RSA     80
#define RSB     144
#define BHI     10240
#define STAGEB  19456
// total static smem: 2*19456 = 38912 < 48K (no attribute needed)

// ---------------- scratch (__device__ globals; R1-identical footprint) -----
__device__ float g_H[(size_t)ROWS_CAP * HID];   // 142.6 MB
__device__ int   g_tok[NEXP * T];
__device__ float g_wt[NEXP * T];
__device__ int   g_cnt[NEXP];
__device__ int   g_off[NEXP];

// ---------------- scalar helpers (no structs, no address-taking) -----------
__device__ __forceinline__ uint32_t smem_u32(const void* p) {
    uint32_t a;
    asm("{ .reg .u64 t; cvta.to.shared.u64 t, %1; cvt.u32.u64 %0, t; }"
        : "=r"(a) : "l"(p));
    return a;
}
// pack (f0,f1) -> bf16x2 hi word + residual lo word (pure scalar asm)
__device__ __forceinline__ void cvt_hilo(float f0, float f1,
                                         uint32_t& hi, uint32_t& lo) {
    asm("cvt.rn.bf16x2.f32 %0, %1, %2;" : "=r"(hi) : "f"(f1), "f"(f0));
    float r0 = f0 - __uint_as_float(hi << 16);
    float r1 = f1 - __uint_as_float(hi & 0xffff0000u);
    asm("cvt.rn.bf16x2.f32 %0, %1, %2;" : "=r"(lo) : "f"(r1), "f"(r0));
}
#define STS128(addr, r0, r1, r2, r3)                                          \
    asm volatile("st.shared.v4.b32 [%0], {%1,%2,%3,%4};"                      \
                 :: "r"(addr), "r"(r0), "r"(r1), "r"(r2), "r"(r3) : "memory")
#define LDSM4(r0, r1, r2, r3, addr)                                           \
    asm volatile("ldmatrix.sync.aligned.m8n8.x4.shared.b16 {%0,%1,%2,%3}, [%4];" \
                 : "=r"(r0), "=r"(r1), "=r"(r2), "=r"(r3) : "r"(addr))
#define LDSM4T(r0, r1, r2, r3, addr)                                          \
    asm volatile("ldmatrix.sync.aligned.m8n8.x4.trans.shared.b16 {%0,%1,%2,%3}, [%4];" \
                 : "=r"(r0), "=r"(r1), "=r"(r2), "=r"(r3) : "r"(addr))
#define MMA4(c0,c1,c2,c3, a0,a1,a2,a3, b0,b1)                                 \
    asm volatile(                                                             \
        "mma.sync.aligned.m16n8k16.row.col.f32.bf16.bf16.f32 "                \
        "{%0,%1,%2,%3}, {%4,%5,%6,%7}, {%8,%9}, {%0,%1,%2,%3};"               \
        : "+f"(c0), "+f"(c1), "+f"(c2), "+f"(c3)                              \
        : "r"(a0), "r"(a1), "r"(a2), "r"(a3), "r"(b0), "r"(b1))

#define GELU(v) (0.5f * (v) * (1.0f + erff((v) * 0.7071067811865476f)))

// ---------------------------------------------------------------------------
// Zero output + expert counters (R1-verbatim)
// ---------------------------------------------------------------------------
__global__ void zero_kernel(float* __restrict__ out) {
    size_t i = (size_t)blockIdx.x * blockDim.x + threadIdx.x;
    const size_t n4 = (size_t)T * DIM / 4;
    float4 z = make_float4(0.f, 0.f, 0.f, 0.f);
    for (size_t p = i; p < n4; p += (size_t)gridDim.x * blockDim.x)
        reinterpret_cast<float4*>(out)[p] = z;
    if (i < NEXP) g_cnt[i] = 0;
}

// ---------------------------------------------------------------------------
// Gating (R1-verbatim): 1 warp/token, logits + top-2 + compaction
// ---------------------------------------------------------------------------
__global__ __launch_bounds__(256) void gate_kernel(
    const float* __restrict__ x, const float* __restrict__ gw,
    const float* __restrict__ gb, float* __restrict__ logits_out)
{
    int warp = (int)((blockIdx.x * blockDim.x + threadIdx.x) >> 5);
    int lane = threadIdx.x & 31;
    if (warp >= T) return;

    const float4* xr = reinterpret_cast<const float4*>(x + (size_t)warp * DIM);
    float acc[NEXP];
#pragma unroll
    for (int e = 0; e < NEXP; e++) acc[e] = 0.f;

    for (int i = lane; i < DIM / 4; i += 32) {
        float4 xv = xr[i];
#pragma unroll
        for (int e = 0; e < NEXP; e++) {
            float4 wv = reinterpret_cast<const float4*>(gw + (size_t)e * DIM)[i];
            acc[e] += xv.x * wv.x + xv.y * wv.y + xv.z * wv.z + xv.w * wv.w;
        }
    }
#pragma unroll
    for (int off = 16; off > 0; off >>= 1)
#pragma unroll
        for (int e = 0; e < NEXP; e++)
            acc[e] += __shfl_xor_sync(0xffffffffu, acc[e], off);

    if (lane == 0) {
        float lg[NEXP];
#pragma unroll
        for (int e = 0; e < NEXP; e++) lg[e] = acc[e] + gb[e];

        int i0 = 0;
#pragma unroll
        for (int e = 1; e < NEXP; e++) if (lg[e] > lg[i0]) i0 = e;
        int i1 = (i0 == 0) ? 1 : 0;
#pragma unroll
        for (int e = 0; e < NEXP; e++)
            if (e != i0 && lg[e] > lg[i1]) i1 = e;

        float w0 = 1.0f / (1.0f + expf(lg[i1] - lg[i0]));
        float w1 = 1.0f - w0;

        int s0 = atomicAdd(&g_cnt[i0], 1);
        g_tok[i0 * T + s0] = warp;  g_wt[i0 * T + s0] = w0;
        int s1 = atomicAdd(&g_cnt[i1], 1);
        g_tok[i1 * T + s1] = warp;  g_wt[i1 * T + s1] = w1;

#pragma unroll
        for (int e = 0; e < NEXP; e++)
            logits_out[(size_t)warp * NEXP + e] = lg[e];
    }
}

__global__ void offsets_kernel() {
    if (threadIdx.x == 0 && blockIdx.x == 0) {
        int off = 0;
        for (int e = 0; e < NEXP; e++) {
            g_off[e] = off;
            off += ((g_cnt[e] + 127) / 128) * 128;
        }
    }
}

// ---------------------------------------------------------------------------
// MoE GEMM: mma.sync bf16 3-term hi/lo split, in-register fp32->bf16 convert,
// classic reg-staged LDG->STS double buffer (NO cp.async, static smem only).
// 256 thr, 8 warps (4M x 2N), warp tile 16x32, CTA tile 64x64, BK=32.
// FFN1: g_H = gelu(gather(x) @ W1_e + b1)   [fp32 H]
// FFN2: out += wt * (H @ W2_e + b2)         [atomicAdd, 2-term commutative]
// ---------------------------------------------------------------------------
template<bool FFN1>
__global__ __launch_bounds__(256) void moe_mma(
    const float* __restrict__ x, const float* __restrict__ W,
    const float* __restrict__ bias, float* __restrict__ out)
{
    constexpr int KTOT = FFN1 ? DIM : HID;
    constexpr int NTOT = FFN1 ? HID : DIM;
    constexpr int NCH  = KTOT / BK;

    int e   = blockIdx.z;
    int cnt = g_cnt[e];
    int m0  = blockIdx.y * BM;
    if (m0 >= cnt) return;
    int n0   = blockIdx.x * BN;
    int base = g_off[e];

    __shared__ __align__(16) char smem[2][STAGEB];
    uint32_t sbase = smem_u32(&smem[0][0]);

    int tid = threadIdx.x, lane = tid & 31, wid = tid >> 5;
    int wm = wid >> 1, wn = wid & 1;

    // ---- loader setup ------------------------------------------------------
    int arow = tid >> 2, aseg = tid & 3;            // A: 64 rows x 4 segs(8 fl)
    const float* pA;
    if (FFN1) {
        int gm  = m0 + arow;
        int tok = g_tok[e * T + (gm < cnt ? gm : cnt - 1)];
        pA = x + (size_t)tok * DIM + aseg * 8;
    } else {
        pA = g_H + (size_t)(base + m0 + arow) * HID + aseg * 8;
    }
    int brow = tid >> 3, bseg = tid & 7;            // B: 32 k-rows x 8 segs
    const float* pB = W + ((size_t)e * KTOT + brow) * NTOT + n0 + bseg * 8;

    uint32_t aoff = (uint32_t)(arow * RSA + aseg * 16);
    uint32_t boff = (uint32_t)(BHI + brow * RSB + bseg * 16);

    float4 va0, va1, vb0, vb1;                      // staging regs

#define LOADR do {                                                            \
        va0 = *(const float4*)pA;  va1 = *(const float4*)(pA + 4);            \
        vb0 = *(const float4*)pB;  vb1 = *(const float4*)(pB + 4);            \
        pA += BK;  pB += (size_t)BK * NTOT;                                   \
    } while (0)

#define STSSTAGE(b) do {                                                      \
        uint32_t s_ = sbase + (uint32_t)((b) * STAGEB);                       \
        uint32_t h0, h1, h2, h3, l0, l1, l2, l3;                              \
        cvt_hilo(va0.x, va0.y, h0, l0);  cvt_hilo(va0.z, va0.w, h1, l1);      \
        cvt_hilo(va1.x, va1.y, h2, l2);  cvt_hilo(va1.z, va1.w, h3, l3);      \
        STS128(s_ + aoff,        h0, h1, h2, h3);                             \
        STS128(s_ + aoff + 5120, l0, l1, l2, l3);                             \
        cvt_hilo(vb0.x, vb0.y, h0, l0);  cvt_hilo(vb0.z, vb0.w, h1, l1);      \
        cvt_hilo(vb1.x, vb1.y, h2, l2);  cvt_hilo(vb1.z, vb1.w, h3, l3);      \
        STS128(s_ + boff,        h0, h1, h2, h3);                             \
        STS128(s_ + boff + 4608, l0, l1, l2, l3);                             \
    } while (0)

    // ---- compute setup -----------------------------------------------------
    uint32_t apos = (uint32_t)((wm * 16 + (lane & 15)) * RSA + (lane >> 4) * 16);
    uint32_t bpos = (uint32_t)(BHI + (lane & 15) * RSB + (lane >> 4) * 16 + wn * 64);

    float c00 = 0.f, c01 = 0.f, c02 = 0.f, c03 = 0.f;
    float c10 = 0.f, c11 = 0.f, c12 = 0.f, c13 = 0.f;
    float c20 = 0.f, c21 = 0.f, c22 = 0.f, c23 = 0.f;
    float c30 = 0.f, c31 = 0.f, c32 = 0.f, c33 = 0.f;
    uint32_t ah0, ah1, ah2, ah3, al0, al1, al2, al3;
    uint32_t bh0, bh1, bh2, bh3, bh4, bh5, bh6, bh7;
    uint32_t bl0, bl1, bl2, bl3, bl4, bl5, bl6, bl7;

#define KSTEP(sb_, ks) do {                                                   \
        uint32_t aA_ = (sb_) + apos + (ks) * 32;                              \
        uint32_t aB_ = (sb_) + bpos + (ks) * (16 * RSB);                      \
        LDSM4 (ah0, ah1, ah2, ah3, aA_);                                      \
        LDSM4T(bh0, bh1, bh2, bh3, aB_);                                      \
        LDSM4T(bh4, bh5, bh6, bh7, aB_ + 32);                                 \
        MMA4(c00,c01,c02,c03, ah0,ah1,ah2,ah3, bh0,bh1);                      \
        MMA4(c10,c11,c12,c13, ah0,ah1,ah2,ah3, bh2,bh3);                      \
        MMA4(c20,c21,c22,c23, ah0,ah1,ah2,ah3, bh4,bh5);                      \
        MMA4(c30,c31,c32,c33, ah0,ah1,ah2,ah3, bh6,bh7);                      \
        LDSM4T(bl0, bl1, bl2, bl3, aB_ + 4608);                               \
        LDSM4T(bl4, bl5, bl6, bl7, aB_ + 4608 + 32);                          \
        MMA4(c00,c01,c02,c03, ah0,ah1,ah2,ah3, bl0,bl1);                      \
        MMA4(c10,c11,c12,c13, ah0,ah1,ah2,ah3, bl2,bl3);                      \
        MMA4(c20,c21,c22,c23, ah0,ah1,ah2,ah3, bl4,bl5);                      \
        MMA4(c30,c31,c32,c33, ah0,ah1,ah2,ah3, bl6,bl7);                      \
        LDSM4 (al0, al1, al2, al3, aA_ + 5120);                               \
        MMA4(c00,c01,c02,c03, al0,al1,al2,al3, bh0,bh1);                      \
        MMA4(c10,c11,c12,c13, al0,al1,al2,al3, bh2,bh3);                      \
        MMA4(c20,c21,c22,c23, al0,al1,al2,al3, bh4,bh5);                      \
        MMA4(c30,c31,c32,c33, al0,al1,al2,al3, bh6,bh7);                      \
    } while (0)

    // ---- pipeline ----------------------------------------------------------
    LOADR;            // stage 0
    STSSTAGE(0);
    LOADR;            // stage 1 (in regs)
    __syncthreads();

#pragma unroll 1
    for (int c = 0; c < NCH; c++) {
        if (c + 1 < NCH) STSSTAGE((c + 1) & 1);
        if (c + 2 < NCH) LOADR;
        uint32_t sb_ = sbase + (uint32_t)((c & 1) * STAGEB);
        KSTEP(sb_, 0);
        KSTEP(sb_, 1);
        __syncthreads();
    }
#undef KSTEP
#undef STSSTAGE
#undef LOADR

    // ---- epilogue ----------------------------------------------------------
    int grp = lane >> 2, qid = lane & 3;
    int gmL = m0 + wm * 16 + grp, gmH = gmL + 8;
    int colB = n0 + wn * 32 + qid * 2;
    const float* bvec = bias + (size_t)e * NTOT;

    if (FFN1) {
#define EP1(tt, x0, x1, x2, x3) do {                                          \
        int col_ = colB + (tt) * 8;                                           \
        float b0_ = __ldg(bvec + col_), b1_ = __ldg(bvec + col_ + 1);         \
        if (gmL < cnt) {                                                      \
            float v0_ = (x0) + b0_, v1_ = (x1) + b1_;                         \
            *(float2*)(g_H + (size_t)(base + gmL) * HID + col_) =             \
                make_float2(GELU(v0_), GELU(v1_));                            \
        }                                                                     \
        if (gmH < cnt) {                                                      \
            float v0_ = (x2) + b0_, v1_ = (x3) + b1_;                         \
            *(float2*)(g_H + (size_t)(base + gmH) * HID + col_) =             \
                make_float2(GELU(v0_), GELU(v1_));                            \
        }                                                                     \
    } while (0)
        EP1(0, c00, c01, c02, c03);
        EP1(1, c10, c11, c12, c13);
        EP1(2, c20, c21, c22, c23);
        EP1(3, c30, c31, c32, c33);
#undef EP1
    } else {
        int tokL = 0, tokH = 0;
        float wL = 0.f, wH = 0.f;
        if (gmL < cnt) { tokL = g_tok[e * T + gmL]; wL = g_wt[e * T + gmL]; }
        if (gmH < cnt) { tokH = g_tok[e * T + gmH]; wH = g_wt[e * T + gmH]; }
#define EP2(tt, x0, x1, x2, x3) do {                                          \
        int col_ = colB + (tt) * 8;                                           \
        float b0_ = __ldg(bvec + col_), b1_ = __ldg(bvec + col_ + 1);         \
        if (gmL < cnt) {                                                      \
            atomicAdd(out + (size_t)tokL * DIM + col_,     ((x0) + b0_) * wL);\
            atomicAdd(out + (size_t)tokL * DIM + col_ + 1, ((x1) + b1_) * wL);\
        }                                                                     \
        if (gmH < cnt) {                                                      \
            atomicAdd(out + (size_t)tokH * DIM + col_,     ((x2) + b0_) * wH);\
            atomicAdd(out + (size_t)tokH * DIM + col_ + 1, ((x3) + b1_) * wH);\
        }                                                                     \
    } while (0)
        EP2(0, c00, c01, c02, c03);
        EP2(1, c10, c11, c12, c13);
        EP2(2, c20, c21, c22, c23);
        EP2(3, c30, c31, c32, c33);
#undef EP2
    }
}

// ---------------------------------------------------------------------------
// Launch
// ---------------------------------------------------------------------------
extern "C" void kernel_launch(void* const* d_in, const int* in_sizes, int n_in,
                              void* d_out, int out_size) {
    const float* x  = (const float*)d_in[0];
    const float* gw = (const float*)d_in[1];
    const float* gb = (const float*)d_in[2];
    const float* W1 = (const float*)d_in[3];
    const float* b1 = (const float*)d_in[4];
    const float* W2 = (const float*)d_in[5];
    const float* b2 = (const float*)d_in[6];
    float* out = (float*)d_out;

    zero_kernel<<<2048, 256>>>(out);
    gate_kernel<<<T / 8, 256>>>(x, gw, gb, out + (size_t)T * DIM);
    offsets_kernel<<<1, 32>>>();

    moe_mma<true ><<<dim3(HID / BN, T / BM, NEXP), 256>>>(x, W1, b1, nullptr);
    moe_mma<false><<<dim3(DIM / BN, T / BM, NEXP), 256>>>(nullptr, W2, b2, out);
}

// round 10
// speedup vs baseline: 2.5166x; 1.3578x over previous
#include <cuda_runtime.h>
#include <math.h>
#include <stdint.h>

#define T     8192
#define DIM   1024
#define NEXP  8
#define HID   2048

#define BM 128
#define BN 128
#define BK 16
#define ROWS_CAP (T * 2 + NEXP * 128)

// smem stage layout (bytes), static:
//   Ahi: 128 rows x 48 = 6144   (16 k bf16 = 32B, pad to 48)
//   Alo: +6144
//   Bhi: 16 k-rows x 272 = 4352 (128 n bf16 = 256B, pad to 272), at 12288
//   Blo: +4352
#define RSA     48
#define RSB     272
#define AHI_OFF 0
#define ALO_D   6144
#define BHI_OFF 12288
#define BLO_D   4352
#define STAGEB  20992
// total static smem: 2*20992 = 41984 < 48K (no attribute needed)

// ---------------- scratch (__device__ globals) ------------------------------
__device__ float g_H[(size_t)ROWS_CAP * HID];   // 142.6 MB
__device__ int   g_tok[NEXP * T];
__device__ float g_wt[NEXP * T];
__device__ int   g_cnt[NEXP];
__device__ int   g_off[NEXP];

// ---------------- scalar helpers (no structs, no address-taking) -----------
__device__ __forceinline__ uint32_t smem_u32(const void* p) {
    uint32_t a;
    asm("{ .reg .u64 t; cvta.to.shared.u64 t, %1; cvt.u32.u64 %0, t; }"
        : "=r"(a) : "l"(p));
    return a;
}
__device__ __forceinline__ void cvt_hilo(float f0, float f1,
                                         uint32_t& hi, uint32_t& lo) {
    asm("cvt.rn.bf16x2.f32 %0, %1, %2;" : "=r"(hi) : "f"(f1), "f"(f0));
    float r0 = f0 - __uint_as_float(hi << 16);
    float r1 = f1 - __uint_as_float(hi & 0xffff0000u);
    asm("cvt.rn.bf16x2.f32 %0, %1, %2;" : "=r"(lo) : "f"(r1), "f"(r0));
}
#define STS128(addr, r0, r1, r2, r3)                                          \
    asm volatile("st.shared.v4.b32 [%0], {%1,%2,%3,%4};"                      \
                 :: "r"(addr), "r"(r0), "r"(r1), "r"(r2), "r"(r3) : "memory")
#define LDSM4(r0, r1, r2, r3, addr)                                           \
    asm volatile("ldmatrix.sync.aligned.m8n8.x4.shared.b16 {%0,%1,%2,%3}, [%4];" \
                 : "=r"(r0), "=r"(r1), "=r"(r2), "=r"(r3) : "r"(addr))
#define LDSM4T(r0, r1, r2, r3, addr)                                          \
    asm volatile("ldmatrix.sync.aligned.m8n8.x4.trans.shared.b16 {%0,%1,%2,%3}, [%4];" \
                 : "=r"(r0), "=r"(r1), "=r"(r2), "=r"(r3) : "r"(addr))
#define MMA4(c0,c1,c2,c3, a0,a1,a2,a3, b0,b1)                                 \
    asm volatile(                                                             \
        "mma.sync.aligned.m16n8k16.row.col.f32.bf16.bf16.f32 "                \
        "{%0,%1,%2,%3}, {%4,%5,%6,%7}, {%8,%9}, {%0,%1,%2,%3};"               \
        : "+f"(c0), "+f"(c1), "+f"(c2), "+f"(c3)                              \
        : "r"(a0), "r"(a1), "r"(a2), "r"(a3), "r"(b0), "r"(b1))

// one term: A (m32 = 2 tiles x 4 regs), B (n64 = 8 sub-tiles x 2 regs) -> 16 MMA4
#define TERM(A0,A1,A2,A3,A4,A5,A6,A7, B0,B1,B2,B3,B4,B5,B6,B7,B8,B9,Ba,Bb,Bc,Bd,Be,Bf) \
    MMA4(c0_0,c0_1,c0_2,c0_3, A0,A1,A2,A3, B0,B1);                            \
    MMA4(c0_4,c0_5,c0_6,c0_7, A4,A5,A6,A7, B0,B1);                            \
    MMA4(c1_0,c1_1,c1_2,c1_3, A0,A1,A2,A3, B2,B3);                            \
    MMA4(c1_4,c1_5,c1_6,c1_7, A4,A5,A6,A7, B2,B3);                            \
    MMA4(c2_0,c2_1,c2_2,c2_3, A0,A1,A2,A3, B4,B5);                            \
    MMA4(c2_4,c2_5,c2_6,c2_7, A4,A5,A6,A7, B4,B5);                            \
    MMA4(c3_0,c3_1,c3_2,c3_3, A0,A1,A2,A3, B6,B7);                            \
    MMA4(c3_4,c3_5,c3_6,c3_7, A4,A5,A6,A7, B6,B7);                            \
    MMA4(c4_0,c4_1,c4_2,c4_3, A0,A1,A2,A3, B8,B9);                            \
    MMA4(c4_4,c4_5,c4_6,c4_7, A4,A5,A6,A7, B8,B9);                            \
    MMA4(c5_0,c5_1,c5_2,c5_3, A0,A1,A2,A3, Ba,Bb);                            \
    MMA4(c5_4,c5_5,c5_6,c5_7, A4,A5,A6,A7, Ba,Bb);                            \
    MMA4(c6_0,c6_1,c6_2,c6_3, A0,A1,A2,A3, Bc,Bd);                            \
    MMA4(c6_4,c6_5,c6_6,c6_7, A4,A5,A6,A7, Bc,Bd);                            \
    MMA4(c7_0,c7_1,c7_2,c7_3, A0,A1,A2,A3, Be,Bf);                            \
    MMA4(c7_4,c7_5,c7_6,c7_7, A4,A5,A6,A7, Be,Bf)

#define GELU(v) (0.5f * (v) * (1.0f + erff((v) * 0.7071067811865476f)))

// ---------------------------------------------------------------------------
// Zero output + expert counters
// ---------------------------------------------------------------------------
__global__ void zero_kernel(float* __restrict__ out) {
    size_t i = (size_t)blockIdx.x * blockDim.x + threadIdx.x;
    const size_t n4 = (size_t)T * DIM / 4;
    float4 z = make_float4(0.f, 0.f, 0.f, 0.f);
    for (size_t p = i; p < n4; p += (size_t)gridDim.x * blockDim.x)
        reinterpret_cast<float4*>(out)[p] = z;
    if (i < NEXP) g_cnt[i] = 0;
}

// ---------------------------------------------------------------------------
// Gating: 1 warp/token, logits + top-2 + compaction
// ---------------------------------------------------------------------------
__global__ __launch_bounds__(256) void gate_kernel(
    const float* __restrict__ x, const float* __restrict__ gw,
    const float* __restrict__ gb, float* __restrict__ logits_out)
{
    int warp = (int)((blockIdx.x * blockDim.x + threadIdx.x) >> 5);
    int lane = threadIdx.x & 31;
    if (warp >= T) return;

    const float4* xr = reinterpret_cast<const float4*>(x + (size_t)warp * DIM);
    float acc[NEXP];
#pragma unroll
    for (int e = 0; e < NEXP; e++) acc[e] = 0.f;

    for (int i = lane; i < DIM / 4; i += 32) {
        float4 xv = xr[i];
#pragma unroll
        for (int e = 0; e < NEXP; e++) {
            float4 wv = reinterpret_cast<const float4*>(gw + (size_t)e * DIM)[i];
            acc[e] += xv.x * wv.x + xv.y * wv.y + xv.z * wv.z + xv.w * wv.w;
        }
    }
#pragma unroll
    for (int off = 16; off > 0; off >>= 1)
#pragma unroll
        for (int e = 0; e < NEXP; e++)
            acc[e] += __shfl_xor_sync(0xffffffffu, acc[e], off);

    if (lane == 0) {
        float lg[NEXP];
#pragma unroll
        for (int e = 0; e < NEXP; e++) lg[e] = acc[e] + gb[e];

        int i0 = 0;
#pragma unroll
        for (int e = 1; e < NEXP; e++) if (lg[e] > lg[i0]) i0 = e;
        int i1 = (i0 == 0) ? 1 : 0;
#pragma unroll
        for (int e = 0; e < NEXP; e++)
            if (e != i0 && lg[e] > lg[i1]) i1 = e;

        float w0 = 1.0f / (1.0f + expf(lg[i1] - lg[i0]));
        float w1 = 1.0f - w0;

        int s0 = atomicAdd(&g_cnt[i0], 1);
        g_tok[i0 * T + s0] = warp;  g_wt[i0 * T + s0] = w0;
        int s1 = atomicAdd(&g_cnt[i1], 1);
        g_tok[i1 * T + s1] = warp;  g_wt[i1 * T + s1] = w1;

#pragma unroll
        for (int e = 0; e < NEXP; e++)
            logits_out[(size_t)warp * NEXP + e] = lg[e];
    }
}

__global__ void offsets_kernel() {
    if (threadIdx.x == 0 && blockIdx.x == 0) {
        int off = 0;
        for (int e = 0; e < NEXP; e++) {
            g_off[e] = off;
            off += ((g_cnt[e] + 127) / 128) * 128;
        }
    }
}

// ---------------------------------------------------------------------------
// MoE GEMM: mma.sync bf16 3-term hi/lo split, in-register fp32->bf16 convert,
// reg-staged LDG->STS double buffer, static smem. 256 thr, 8 warps (4M x 2N),
// warp tile 32x64, CTA tile 128x128, BK=16.
// FFN1: g_H = gelu(gather(x) @ W1_e + b1)   [fp32 H]
// FFN2: out += wt * (H @ W2_e + b2)         [atomicAdd, commutative 2-term]
// ---------------------------------------------------------------------------
template<bool FFN1>
__global__ __launch_bounds__(256) void moe_mma(
    const float* __restrict__ x, const float* __restrict__ W,
    const float* __restrict__ bias, float* __restrict__ out)
{
    constexpr int KTOT = FFN1 ? DIM : HID;
    constexpr int NTOT = FFN1 ? HID : DIM;
    constexpr int NCH  = KTOT / BK;

    int e   = blockIdx.z;
    int cnt = g_cnt[e];
    int m0  = blockIdx.y * BM;
    if (m0 >= cnt) return;
    int n0   = blockIdx.x * BN;
    int base = g_off[e];

    __shared__ __align__(128) char smem[2][STAGEB];
    uint32_t sbase = smem_u32(&smem[0][0]);

    int tid = threadIdx.x, lane = tid & 31, wid = tid >> 5;
    int wm = wid >> 1, wn = wid & 1;

    // ---- loader setup ------------------------------------------------------
    int arow = tid >> 1, aseg = tid & 1;            // A: 128 rows x 2 segs (8 fl)
    const float* pA;
    if (FFN1) {
        int gm  = m0 + arow;
        int tok = g_tok[e * T + (gm < cnt ? gm : cnt - 1)];
        pA = x + (size_t)tok * DIM + aseg * 8;
    } else {
        pA = g_H + (size_t)(base + m0 + arow) * HID + aseg * 8;
    }
    int brow = tid >> 4, bseg = tid & 15;           // B: 16 k-rows x 16 segs
    const float* pB = W + ((size_t)e * KTOT + brow) * NTOT + n0 + bseg * 8;

    uint32_t aoff = (uint32_t)(arow * RSA + aseg * 16);
    uint32_t boff = (uint32_t)(BHI_OFF + brow * RSB + bseg * 16);

    float4 va0, va1, vb0, vb1;

#define LOADR do {                                                            \
        va0 = *(const float4*)pA;  va1 = *(const float4*)(pA + 4);            \
        vb0 = *(const float4*)pB;  vb1 = *(const float4*)(pB + 4);            \
        pA += BK;  pB += (size_t)BK * NTOT;                                   \
    } while (0)

#define STSSTAGE(b) do {                                                      \
        uint32_t s_ = sbase + (uint32_t)((b) * STAGEB);                       \
        uint32_t h0, h1, h2, h3, l0, l1, l2, l3;                              \
        cvt_hilo(va0.x, va0.y, h0, l0);  cvt_hilo(va0.z, va0.w, h1, l1);      \
        cvt_hilo(va1.x, va1.y, h2, l2);  cvt_hilo(va1.z, va1.w, h3, l3);      \
        STS128(s_ + aoff,         h0, h1, h2, h3);                            \
        STS128(s_ + aoff + ALO_D, l0, l1, l2, l3);                            \
        cvt_hilo(vb0.x, vb0.y, h0, l0);  cvt_hilo(vb0.z, vb0.w, h1, l1);      \
        cvt_hilo(vb1.x, vb1.y, h2, l2);  cvt_hilo(vb1.z, vb1.w, h3, l3);      \
        STS128(s_ + boff,         h0, h1, h2, h3);                            \
        STS128(s_ + boff + BLO_D, l0, l1, l2, l3);                            \
    } while (0)

    // ---- compute setup -----------------------------------------------------
    uint32_t apos = (uint32_t)((wm * 32 + (lane & 15)) * RSA + (lane >> 4) * 16);
    uint32_t bpos = (uint32_t)(BHI_OFF + (lane & 15) * RSB + (lane >> 4) * 16
                               + wn * 128);

    float c0_0=0,c0_1=0,c0_2=0,c0_3=0,c0_4=0,c0_5=0,c0_6=0,c0_7=0;
    float c1_0=0,c1_1=0,c1_2=0,c1_3=0,c1_4=0,c1_5=0,c1_6=0,c1_7=0;
    float c2_0=0,c2_1=0,c2_2=0,c2_3=0,c2_4=0,c2_5=0,c2_6=0,c2_7=0;
    float c3_0=0,c3_1=0,c3_2=0,c3_3=0,c3_4=0,c3_5=0,c3_6=0,c3_7=0;
    float c4_0=0,c4_1=0,c4_2=0,c4_3=0,c4_4=0,c4_5=0,c4_6=0,c4_7=0;
    float c5_0=0,c5_1=0,c5_2=0,c5_3=0,c5_4=0,c5_5=0,c5_6=0,c5_7=0;
    float c6_0=0,c6_1=0,c6_2=0,c6_3=0,c6_4=0,c6_5=0,c6_6=0,c6_7=0;
    float c7_0=0,c7_1=0,c7_2=0,c7_3=0,c7_4=0,c7_5=0,c7_6=0,c7_7=0;

    uint32_t ah0, ah1, ah2, ah3, ah4, ah5, ah6, ah7;
    uint32_t bh0, bh1, bh2, bh3, bh4, bh5, bh6, bh7;
    uint32_t bh8, bh9, bha, bhb, bhc, bhd, bhe, bhf;
    uint32_t bl0, bl1, bl2, bl3, bl4, bl5, bl6, bl7;
    uint32_t bl8, bl9, bla, blb, blc, bld, ble, blf;

#define KSTEP(sb_) do {                                                       \
        uint32_t aA_ = (sb_) + apos;                                          \
        uint32_t aB_ = (sb_) + bpos;                                          \
        LDSM4 (ah0, ah1, ah2, ah3, aA_);                                      \
        LDSM4 (ah4, ah5, ah6, ah7, aA_ + 16 * RSA);                           \
        LDSM4T(bh0, bh1, bh2, bh3, aB_);                                      \
        LDSM4T(bh4, bh5, bh6, bh7, aB_ + 32);                                 \
        LDSM4T(bh8, bh9, bha, bhb, aB_ + 64);                                 \
        LDSM4T(bhc, bhd, bhe, bhf, aB_ + 96);                                 \
        TERM(ah0,ah1,ah2,ah3,ah4,ah5,ah6,ah7,                                 \
             bh0,bh1,bh2,bh3,bh4,bh5,bh6,bh7,bh8,bh9,bha,bhb,bhc,bhd,bhe,bhf);\
        LDSM4T(bl0, bl1, bl2, bl3, aB_ + BLO_D);                              \
        LDSM4T(bl4, bl5, bl6, bl7, aB_ + BLO_D + 32);                         \
        LDSM4T(bl8, bl9, bla, blb, aB_ + BLO_D + 64);                         \
        LDSM4T(blc, bld, ble, blf, aB_ + BLO_D + 96);                         \
        TERM(ah0,ah1,ah2,ah3,ah4,ah5,ah6,ah7,                                 \
             bl0,bl1,bl2,bl3,bl4,bl5,bl6,bl7,bl8,bl9,bla,blb,blc,bld,ble,blf);\
        LDSM4 (ah0, ah1, ah2, ah3, aA_ + ALO_D);                              \
        LDSM4 (ah4, ah5, ah6, ah7, aA_ + ALO_D + 16 * RSA);                   \
        TERM(ah0,ah1,ah2,ah3,ah4,ah5,ah6,ah7,                                 \
             bh0,bh1,bh2,bh3,bh4,bh5,bh6,bh7,bh8,bh9,bha,bhb,bhc,bhd,bhe,bhf);\
    } while (0)

    // ---- pipeline ----------------------------------------------------------
    LOADR;            // stage 0
    STSSTAGE(0);
    LOADR;            // stage 1 (in regs)
    __syncthreads();

#pragma unroll 1
    for (int c = 0; c < NCH; c++) {
        if (c + 1 < NCH) STSSTAGE((c + 1) & 1);
        if (c + 2 < NCH) LOADR;
        KSTEP(sbase + (uint32_t)((c & 1) * STAGEB));
        __syncthreads();
    }
#undef KSTEP
#undef STSSTAGE
#undef LOADR

    // ---- epilogue ----------------------------------------------------------
    int grp = lane >> 2, qid = lane & 3;
    int r0 = m0 + wm * 32 + grp;          // rows r0, r0+8, r0+16, r0+24
    int colB = n0 + wn * 64 + qid * 2;
    const float* bvec = bias + (size_t)e * NTOT;

    if (FFN1) {
#define EP1(J, y0,y1,y2,y3,y4,y5,y6,y7) do {                                  \
        int col_ = colB + (J) * 8;                                            \
        float b0_ = __ldg(bvec + col_), b1_ = __ldg(bvec + col_ + 1);         \
        if (r0 < cnt)      { float u0=(y0)+b0_, u1=(y1)+b1_;                  \
            *(float2*)(g_H + (size_t)(base + r0) * HID + col_) =              \
                make_float2(GELU(u0), GELU(u1)); }                            \
        if (r0 + 8 < cnt)  { float u0=(y2)+b0_, u1=(y3)+b1_;                  \
            *(float2*)(g_H + (size_t)(base + r0 + 8) * HID + col_) =          \
                make_float2(GELU(u0), GELU(u1)); }                            \
        if (r0 + 16 < cnt) { float u0=(y4)+b0_, u1=(y5)+b1_;                  \
            *(float2*)(g_H + (size_t)(base + r0 + 16) * HID + col_) =         \
                make_float2(GELU(u0), GELU(u1)); }                            \
        if (r0 + 24 < cnt) { float u0=(y6)+b0_, u1=(y7)+b1_;                  \
            *(float2*)(g_H + (size_t)(base + r0 + 24) * HID + col_) =         \
                make_float2(GELU(u0), GELU(u1)); }                            \
    } while (0)
        EP1(0, c0_0,c0_1,c0_2,c0_3,c0_4,c0_5,c0_6,c0_7);
        EP1(1, c1_0,c1_1,c1_2,c1_3,c1_4,c1_5,c1_6,c1_7);
        EP1(2, c2_0,c2_1,c2_2,c2_3,c2_4,c2_5,c2_6,c2_7);
        EP1(3, c3_0,c3_1,c3_2,c3_3,c3_4,c3_5,c3_6,c3_7);
        EP1(4, c4_0,c4_1,c4_2,c4_3,c4_4,c4_5,c4_6,c4_7);
        EP1(5, c5_0,c5_1,c5_2,c5_3,c5_4,c5_5,c5_6,c5_7);
        EP1(6, c6_0,c6_1,c6_2,c6_3,c6_4,c6_5,c6_6,c6_7);
        EP1(7, c7_0,c7_1,c7_2,c7_3,c7_4,c7_5,c7_6,c7_7);
#undef EP1
    } else {
        int tk0 = 0, tk1 = 0, tk2 = 0, tk3 = 0;
        float w0_ = 0.f, w1_ = 0.f, w2_ = 0.f, w3_ = 0.f;
        if (r0 < cnt)      { tk0 = g_tok[e*T + r0];      w0_ = g_wt[e*T + r0]; }
        if (r0 + 8 < cnt)  { tk1 = g_tok[e*T + r0 + 8];  w1_ = g_wt[e*T + r0 + 8]; }
        if (r0 + 16 < cnt) { tk2 = g_tok[e*T + r0 + 16]; w2_ = g_wt[e*T + r0 + 16]; }
        if (r0 + 24 < cnt) { tk3 = g_tok[e*T + r0 + 24]; w3_ = g_wt[e*T + r0 + 24]; }
#define EP2(J, y0,y1,y2,y3,y4,y5,y6,y7) do {                                  \
        int col_ = colB + (J) * 8;                                            \
        float b0_ = __ldg(bvec + col_), b1_ = __ldg(bvec + col_ + 1);         \
        if (r0 < cnt) {                                                       \
            atomicAdd(out + (size_t)tk0 * DIM + col_,     ((y0)+b0_) * w0_);  \
            atomicAdd(out + (size_t)tk0 * DIM + col_ + 1, ((y1)+b1_) * w0_);  \
        }                                                                     \
        if (r0 + 8 < cnt) {                                                   \
            atomicAdd(out + (size_t)tk1 * DIM + col_,     ((y2)+b0_) * w1_);  \
            atomicAdd(out + (size_t)tk1 * DIM + col_ + 1, ((y3)+b1_) * w1_);  \
        }                                                                     \
        if (r0 + 16 < cnt) {                                                  \
            atomicAdd(out + (size_t)tk2 * DIM + col_,     ((y4)+b0_) * w2_);  \
            atomicAdd(out + (size_t)tk2 * DIM + col_ + 1, ((y5)+b1_) * w2_);  \
        }                                                                     \
        if (r0 + 24 < cnt) {                                                  \
            atomicAdd(out + (size_t)tk3 * DIM + col_,     ((y6)+b0_) * w3_);  \
            atomicAdd(out + (size_t)tk3 * DIM + col_ + 1, ((y7)+b1_) * w3_);  \
        }                                                                     \
    } while (0)
        EP2(0, c0_0,c0_1,c0_2,c0_3,c0_4,c0_5,c0_6,c0_7);
        EP2(1, c1_0,c1_1,c1_2,c1_3,c1_4,c1_5,c1_6,c1_7);
        EP2(2, c2_0,c2_1,c2_2,c2_3,c2_4,c2_5,c2_6,c2_7);
        EP2(3, c3_0,c3_1,c3_2,c3_3,c3_4,c3_5,c3_6,c3_7);
        EP2(4, c4_0,c4_1,c4_2,c4_3,c4_4,c4_5,c4_6,c4_7);
        EP2(5, c5_0,c5_1,c5_2,c5_3,c5_4,c5_5,c5_6,c5_7);
        EP2(6, c6_0,c6_1,c6_2,c6_3,c6_4,c6_5,c6_6,c6_7);
        EP2(7, c7_0,c7_1,c7_2,c7_3,c7_4,c7_5,c7_6,c7_7);
#undef EP2
    }
}

// ---------------------------------------------------------------------------
// Launch
// ---------------------------------------------------------------------------
extern "C" void kernel_launch(void* const* d_in, const int* in_sizes, int n_in,
                              void* d_out, int out_size) {
    const float* x  = (const float*)d_in[0];
    const float* gw = (const float*)d_in[1];
    const float* gb = (const float*)d_in[2];
    const float* W1 = (const float*)d_in[3];
    const float* b1 = (const float*)d_in[4];
    const float* W2 = (const float*)d_in[5];
    const float* b2 = (const float*)d_in[6];
    float* out = (float*)d_out;

    zero_kernel<<<2048, 256>>>(out);
    gate_kernel<<<T / 8, 256>>>(x, gw, gb, out + (size_t)T * DIM);
    offsets_kernel<<<1, 32>>>();

    moe_mma<true ><<<dim3(HID / BN, T / BM, NEXP), 256>>>(x, W1, b1, nullptr);
    moe_mma<false><<<dim3(DIM / BN, T / BM, NEXP), 256>>>(nullptr, W2, b2, out);
}